// round 15
// baseline (speedup 1.0000x reference)
#include <cuda_runtime.h>
#include <cuda_fp16.h>
#include <cstdint>

#define N_I 500000
#define N_H 200000
#define F_I 32
#define F_H 16
#define EF  8
#define TPB 256

// Packed per-source-node table entry: 32 bytes, 32B-aligned -> 1 L2 sector,
// fetched with a single 256-bit load in the edge kernel.
__device__ __align__(32) uint4 g_tab_h[(size_t)N_H * 2];
__device__ __align__(32) uint4 g_tab_i[(size_t)N_I * 2];

__device__ __forceinline__ unsigned pack2(float a, float b) {
    __half2 h = __floats2half2_rn(a, b);
    return *reinterpret_cast<unsigned*>(&h);
}

// ---------------------------------------------------------------------------
// Kernel 1: one pass over node features, smem-staged for coalescing.
//   blocks [0, BI)      : indivi (256 nodes/block) -> tab_i + out root term
//   blocks [BI, BI+BH)  : house  (256 nodes/block) -> tab_h
// x reads use evict-first (.cs): pure stream, and must not evict the tab
// lines that kernel 2 will gather from L2.
// ---------------------------------------------------------------------------
__global__ void fused_precompute_kernel(
    const float* __restrict__ x_i, const float* __restrict__ x_h,
    const float* __restrict__ W_i,  const float* __restrict__ b_i,
    const float* __restrict__ W_h,  const float* __restrict__ b_h,
    const float* __restrict__ wrh,  const float* __restrict__ wri,
    const float* __restrict__ bias_h, const float* __restrict__ bias_i,
    uint4* __restrict__ tab_i, uint4* __restrict__ tab_h,
    float* __restrict__ out, int BI)
{
    __shared__ float tile[TPB * 33];   // indivi rows: 33 words; house reuses with 17
    __shared__ float Ws[F_I * EF];
    __shared__ float bs[F_I];
    __shared__ float wr[F_I];

    const int tid = threadIdx.x;

    if (blockIdx.x < BI) {
        // ---- indivi ----
        for (int t = tid; t < F_I * EF; t += TPB) Ws[t] = W_i[t];
        if (tid < F_I) {
            bs[tid] = b_i[tid];
            wr[tid] = wrh[tid] + wri[tid];
        }

        int base = blockIdx.x * TPB;
        int cnt  = min(TPB, N_I - base);

        const float4* xg = (const float4*)x_i + (size_t)base * (F_I / 4);
        int total4 = cnt * (F_I / 4);
        for (int i = tid; i < total4; i += TPB) {
            float4 v = __ldcs(xg + i);
            float* dstp = tile + (i >> 3) * 33 + (i & 7) * 4;
            dstp[0] = v.x; dstp[1] = v.y; dstp[2] = v.z; dstp[3] = v.w;
        }
        __syncthreads();

        if (tid < cnt) {
            const float* xr = tile + tid * 33;
            float p[EF];
            #pragma unroll
            for (int k = 0; k < EF; k++) p[k] = 0.f;
            float q = 0.f, r = 0.f;

            #pragma unroll
            for (int f = 0; f < F_I; f++) {
                float a = xr[f];
                q += a * bs[f];
                r += a * wr[f];
                #pragma unroll
                for (int k = 0; k < EF; k++) p[k] += a * Ws[f * EF + k];
            }

            int n = base + tid;
            uint4 e0, e1;
            e0.x = pack2(p[0], p[1]); e0.y = pack2(p[2], p[3]);
            e0.z = pack2(p[4], p[5]); e0.w = pack2(p[6], p[7]);
            e1.x = __float_as_uint(q); e1.y = 0; e1.z = 0; e1.w = 0;
            tab_i[(size_t)n * 2]     = e0;
            tab_i[(size_t)n * 2 + 1] = e1;
            out[n] = r + bias_h[0] + bias_i[0];
        }
    } else {
        // ---- house ----
        for (int t = tid; t < F_H * EF; t += TPB) Ws[t] = W_h[t];
        if (tid < F_H) bs[tid] = b_h[tid];

        int base = (blockIdx.x - BI) * TPB;
        int cnt  = min(TPB, N_H - base);

        const float4* xg = (const float4*)x_h + (size_t)base * (F_H / 4);
        int total4 = cnt * (F_H / 4);
        for (int i = tid; i < total4; i += TPB) {
            float4 v = __ldcs(xg + i);
            float* dstp = tile + (i >> 2) * 17 + (i & 3) * 4;
            dstp[0] = v.x; dstp[1] = v.y; dstp[2] = v.z; dstp[3] = v.w;
        }
        __syncthreads();

        if (tid < cnt) {
            const float* xr = tile + tid * 17;
            float p[EF];
            #pragma unroll
            for (int k = 0; k < EF; k++) p[k] = 0.f;
            float q = 0.f;

            #pragma unroll
            for (int f = 0; f < F_H; f++) {
                float a = xr[f];
                q += a * bs[f];
                #pragma unroll
                for (int k = 0; k < EF; k++) p[k] += a * Ws[f * EF + k];
            }

            int n = base + tid;
            uint4 e0, e1;
            e0.x = pack2(p[0], p[1]); e0.y = pack2(p[2], p[3]);
            e0.z = pack2(p[4], p[5]); e0.w = pack2(p[6], p[7]);
            e1.x = __float_as_uint(q); e1.y = 0; e1.z = 0; e1.w = 0;
            tab_h[(size_t)n * 2]     = e0;
            tab_h[(size_t)n * 2 + 1] = e1;
        }
    }
}

// ---------------------------------------------------------------------------
// Kernel 2: both edge relations.
//   ea stream : LDG.256 evict-first (pure stream)
//   table     : LDG.256 non-coherent + L2::evict_last (pin tables in L2)
//   atomic    : REDG to out
// ---------------------------------------------------------------------------
__device__ __forceinline__ void edge_work(
    const float* __restrict__ ea, const int* __restrict__ src,
    const int* __restrict__ dst, const uint4* __restrict__ tab,
    float* __restrict__ out, int e, int E)
{
    if (e >= E) return;

    int s = __ldcs(src + e);
    int d = __ldcs(dst + e);

    const void* eap = (const void*)(ea + (size_t)e * EF);
    unsigned a0, a1, a2, a3, a4, a5, a6, a7;
    asm volatile(
        "ld.global.cs.v8.b32 {%0,%1,%2,%3,%4,%5,%6,%7}, [%8];"
        : "=r"(a0), "=r"(a1), "=r"(a2), "=r"(a3),
          "=r"(a4), "=r"(a5), "=r"(a6), "=r"(a7)
        : "l"(eap));

    const void* tp = (const void*)(tab + (size_t)s * 2);
    unsigned r0, r1, r2, r3, r4, r5, r6, r7;
    asm volatile(
        "ld.global.nc.L2::evict_last.v8.b32 {%0,%1,%2,%3,%4,%5,%6,%7}, [%8];"
        : "=r"(r0), "=r"(r1), "=r"(r2), "=r"(r3),
          "=r"(r4), "=r"(r5), "=r"(r6), "=r"(r7)
        : "l"(tp));

    float2 f0 = __half22float2(*reinterpret_cast<__half2*>(&r0));
    float2 f1 = __half22float2(*reinterpret_cast<__half2*>(&r1));
    float2 f2 = __half22float2(*reinterpret_cast<__half2*>(&r2));
    float2 f3 = __half22float2(*reinterpret_cast<__half2*>(&r3));
    float  q  = __uint_as_float(r4);

    float msg = __uint_as_float(a0) * f0.x + __uint_as_float(a1) * f0.y
              + __uint_as_float(a2) * f1.x + __uint_as_float(a3) * f1.y
              + __uint_as_float(a4) * f2.x + __uint_as_float(a5) * f2.y
              + __uint_as_float(a6) * f3.x + __uint_as_float(a7) * f3.y + q;

    atomicAdd(out + d, msg);
}

__global__ void fused_edge_kernel(
    const float* __restrict__ ea1, const int* __restrict__ src1,
    const int* __restrict__ dst1, const uint4* __restrict__ tab1, int E1,
    const float* __restrict__ ea2, const int* __restrict__ src2,
    const int* __restrict__ dst2, const uint4* __restrict__ tab2, int E2,
    float* __restrict__ out, int B1)
{
    if (blockIdx.x < B1) {
        int e = blockIdx.x * blockDim.x + threadIdx.x;
        edge_work(ea1, src1, dst1, tab1, out, e, E1);
    } else {
        int e = (blockIdx.x - B1) * blockDim.x + threadIdx.x;
        edge_work(ea2, src2, dst2, tab2, out, e, E2);
    }
}

extern "C" void kernel_launch(void* const* d_in, const int* in_sizes, int n_in,
                              void* d_out, int out_size)
{
    const float* x_indivi   = (const float*)d_in[0];
    const float* x_house    = (const float*)d_in[1];
    const float* ea_h2i     = (const float*)d_in[2];
    const float* ea_i2i     = (const float*)d_in[3];
    const float* W_edge_h2i = (const float*)d_in[4];
    const float* b_edge_h2i = (const float*)d_in[5];
    const float* W_edge_i2i = (const float*)d_in[6];
    const float* b_edge_i2i = (const float*)d_in[7];
    const float* W_root_h2i = (const float*)d_in[8];
    const float* bias_h2i   = (const float*)d_in[9];
    const float* W_root_i2i = (const float*)d_in[10];
    const float* bias_i2i   = (const float*)d_in[11];
    const int*   src_h2i    = (const int*)d_in[12];
    const int*   dst_h2i    = (const int*)d_in[13];
    const int*   src_i2i    = (const int*)d_in[14];
    const int*   dst_i2i    = (const int*)d_in[15];

    float* out = (float*)d_out;

    const int E1 = in_sizes[12];
    const int E2 = in_sizes[14];

    uint4* tab_h = nullptr;
    uint4* tab_i = nullptr;
    cudaGetSymbolAddress((void**)&tab_h, g_tab_h);
    cudaGetSymbolAddress((void**)&tab_i, g_tab_i);

    // Kernel 1: fused precompute + root init (smem-staged coalesced)
    {
        int BI = (N_I + TPB - 1) / TPB;   // 1954
        int BH = (N_H + TPB - 1) / TPB;   // 782
        fused_precompute_kernel<<<BI + BH, TPB>>>(
            x_indivi, x_house,
            W_edge_i2i, b_edge_i2i, W_edge_h2i, b_edge_h2i,
            W_root_h2i, W_root_i2i, bias_h2i, bias_i2i,
            tab_i, tab_h, out, BI);
    }
    // Kernel 2: both edge relations
    {
        int B1 = (E1 + TPB - 1) / TPB;
        int B2 = (E2 + TPB - 1) / TPB;
        fused_edge_kernel<<<B1 + B2, TPB>>>(
            ea_h2i, src_h2i, dst_h2i, tab_h, E1,
            ea_i2i, src_i2i, dst_i2i, tab_i, E2,
            out, B1);
    }
}